// round 15
// baseline (speedup 1.0000x reference)
#include <cuda_runtime.h>
#include <cuda_bf16.h>
#include <cstdint>

// Problem constants (match reference)
#define E_CNT   800000
#define N_NODES 50000
#define N_NF    16
#define N_EF    8
#define FEAT    40      // 2*N_NF + N_EF
#define FEATP   48      // padded to 8-half chunks
#define HID     300
#define HIDP    304     // padded
#define MSGD    128
#define NGRAPH  64
#define NPRED   8

// ------------------------------------------------------------------
// Scratch (device globals; zero-initialized, pads stay 0 forever)
// ------------------------------------------------------------------
__device__ __nv_bfloat16 g_bbuf1[(size_t)E_CNT * HIDP];
__device__ __nv_bfloat16 g_bbuf2[(size_t)E_CNT * HIDP];
__device__ float g_aggr[(size_t)N_NODES * MSGD];
__device__ float g_gsum[NGRAPH * HID];
__device__ float g_gcnt[NGRAPH];
// bf16 weights, transposed+padded [N][Kp]:
//   mw1[300][48], mw2/mw3[300][304], mw4[128][304],
//   nw2/nw3/nw4[300][304]
#define WBF_TOTAL (300*FEATP + 2*300*HIDP + 128*HIDP + 3*300*HIDP)
__device__ __nv_bfloat16 g_wbf[WBF_TOTAL];
// node L1 weight: fp32 tf32-rounded, transposed [300][128]
__device__ float g_wnd[300 * 128];

__device__ __forceinline__ uint32_t f2tf32(float v) {
    uint32_t t;
    asm("cvt.rna.tf32.f32 %0, %1;" : "=r"(t) : "f"(v));
    return t;
}
__device__ __forceinline__ uint32_t pack_bf2(float a, float b) {
    __nv_bfloat162 p = __floats2bfloat162_rn(a, b);
    return *reinterpret_cast<uint32_t*>(&p);
}

// ------------------------------------------------------------------
// Merged weight prep: grid.y = weight id (0-6 bf16, 7 tf32 nw1)
// ------------------------------------------------------------------
struct PrepArgs {
    const float* src[8];
    __nv_bfloat16* dstb[7];
    float* dstf;
    int K[8], N[8], Kp[7];
};

__global__ void prep_all_kernel(PrepArgs pa)
{
    int w = blockIdx.y;
    int i = blockIdx.x * blockDim.x + threadIdx.x;
    if (w < 7) {
        int K = pa.K[w], N = pa.N[w], Kp = pa.Kp[w];
        if (i >= N * Kp) return;
        int n = i / Kp, k = i % Kp;
        pa.dstb[w][i] = (k < K) ? __float2bfloat16(pa.src[w][(size_t)k * N + n])
                                : __float2bfloat16(0.f);
    } else {
        int K = pa.K[7], N = pa.N[7];
        if (i >= K * N) return;
        int k = i / N, n = i % N;
        pa.dstf[(size_t)n * K + k] = __uint_as_float(f2tf32(pa.src[7][i]));
    }
}

// ------------------------------------------------------------------
// Async-copy / ldmatrix / atomic helpers
// ------------------------------------------------------------------
__device__ __forceinline__ void cp_async16(void* sptr, const void* gptr, bool pred)
{
    uint32_t saddr = (uint32_t)__cvta_generic_to_shared(sptr);
    int sz = pred ? 16 : 0;  // src-size 0 => 16B of zeros written
    asm volatile("cp.async.cg.shared.global [%0], [%1], 16, %2;\n"
                 :: "r"(saddr), "l"(gptr), "r"(sz));
}
__device__ __forceinline__ void cp_async_commit() {
    asm volatile("cp.async.commit_group;\n" ::: "memory");
}
template<int N_> __device__ __forceinline__ void cp_async_wait() {
    asm volatile("cp.async.wait_group %0;\n" :: "n"(N_) : "memory");
}
__device__ __forceinline__ void ldsm_x4(uint32_t& r0, uint32_t& r1,
                                        uint32_t& r2, uint32_t& r3, uint32_t saddr)
{
    asm volatile("ldmatrix.sync.aligned.m8n8.x4.shared.b16 {%0,%1,%2,%3}, [%4];\n"
                 : "=r"(r0), "=r"(r1), "=r"(r2), "=r"(r3) : "r"(saddr));
}
__device__ __forceinline__ void red_add_v2(float* addr, float a, float b)
{
    asm volatile("red.global.add.v2.f32 [%0], {%1, %2};\n"
                 :: "l"(addr), "f"(a), "f"(b) : "memory");
}

#define BM 128
#define BN 64
#define SSB 72   // smem row stride in halves (144B): LDSM conflict-free

// ==================================================================
// Fused gather + edge L1 GEMM (K=48 = one k-tile, no k-loop):
// A[128 edges][48] gathered from x[dst]/x[src]/ea straight into smem
// (identical bf16 packing as the old gather kernel); W tile cp.async;
// 3 k-steps of LDSM+MMA; bias+ReLU bf16 epilogue.
// ==================================================================
#define KL1 48

__global__ __launch_bounds__(256, 4)
void gemm_l1_fused(const float* __restrict__ x,
                   const int* __restrict__ srcI,
                   const int* __restrict__ dstI,
                   const float* __restrict__ ea,
                   const __nv_bfloat16* __restrict__ Wt,   // [300][48]
                   const float* __restrict__ bias,
                   __nv_bfloat16* __restrict__ C,
                   int M, int N, int ldc)
{
    __shared__ __align__(16) __nv_bfloat16 As[BM][SSB];
    __shared__ __align__(16) __nv_bfloat16 Ws[BN][SSB];

    const int tid  = threadIdx.x;
    const int warp = tid >> 5;
    const int lane = tid & 31;
    const int wm = (warp & 3) * 32;
    const int wn = (warp >> 2) * 32;
    const int n0 = blockIdx.x * BN;
    const int m0 = blockIdx.y * BM;

    const int lr = lane >> 2;
    const int lc = lane & 3;

    const int aRowOff = lane & 15;
    const int aColOff = (lane >> 4) << 3;
    const int t8 = lane >> 3, r8 = lane & 7;
    const int bRowOff = ((t8 >> 1) << 3) + r8;
    const int bColOff = (t8 & 1) << 3;

    const uint32_t As32 = (uint32_t)__cvta_generic_to_shared(&As[0][0]);
    const uint32_t Ws32 = (uint32_t)__cvta_generic_to_shared(&Ws[0][0]);

    // W tile: 64 rows x 6 chunks of 16B
#pragma unroll
    for (int i = 0; i < 2; i++) {
        int c = tid + i * 256;
        if (c < BN * 6) {
            int nn = c / 6, kc = (c % 6) * 8;
            bool ok = (n0 + nn) < N;
            cp_async16(&Ws[nn][kc], Wt + (size_t)(ok ? (n0 + nn) : 0) * KL1 + kc, ok);
        }
    }
    cp_async_commit();

    // Gathered A tile: 128 edges x 6 chunks (c5 = zero pad)
#pragma unroll
    for (int i = 0; i < 3; i++) {
        int u = tid + i * 256;
        int erow = u / 6, c = u % 6;
        int row = m0 + erow;
        uint4 o = make_uint4(0u, 0u, 0u, 0u);
        if (row < M && c < 5) {
            float4 v0, v1;
            if (c < 4) {
                int node = (c < 2) ? dstI[row] : srcI[row];
                const float4* xp = reinterpret_cast<const float4*>(x)
                                   + (size_t)node * 4 + (c & 1) * 2;
                v0 = xp[0]; v1 = xp[1];
            } else {
                const float4* epp = reinterpret_cast<const float4*>(ea)
                                    + (size_t)row * 2;
                v0 = epp[0]; v1 = epp[1];
            }
            o.x = pack_bf2(v0.x, v0.y); o.y = pack_bf2(v0.z, v0.w);
            o.z = pack_bf2(v1.x, v1.y); o.w = pack_bf2(v1.z, v1.w);
        }
        *reinterpret_cast<uint4*>(&As[erow][c * 8]) = o;
    }

    float acc[2][4][4];
#pragma unroll
    for (int mi = 0; mi < 2; mi++)
#pragma unroll
        for (int ni = 0; ni < 4; ni++)
#pragma unroll
            for (int r = 0; r < 4; r++) acc[mi][ni][r] = 0.f;

    cp_async_wait<0>();
    __syncthreads();

#pragma unroll
    for (int ks = 0; ks < KL1; ks += 16) {
        uint32_t a[2][4], b[4][2];
#pragma unroll
        for (int mi = 0; mi < 2; mi++) {
            uint32_t addr = As32 +
                (uint32_t)(((wm + mi * 16 + aRowOff) * SSB + ks + aColOff) * 2);
            ldsm_x4(a[mi][0], a[mi][1], a[mi][2], a[mi][3], addr);
        }
#pragma unroll
        for (int p = 0; p < 2; p++) {
            uint32_t addr = Ws32 +
                (uint32_t)(((wn + p * 16 + bRowOff) * SSB + ks + bColOff) * 2);
            ldsm_x4(b[2 * p][0], b[2 * p][1], b[2 * p + 1][0], b[2 * p + 1][1], addr);
        }
#pragma unroll
        for (int mi = 0; mi < 2; mi++)
#pragma unroll
            for (int ni = 0; ni < 4; ni++) {
                asm volatile(
                    "mma.sync.aligned.m16n8k16.row.col.f32.bf16.bf16.f32 "
                    "{%0,%1,%2,%3}, {%4,%5,%6,%7}, {%8,%9}, {%0,%1,%2,%3};\n"
                    : "+f"(acc[mi][ni][0]), "+f"(acc[mi][ni][1]),
                      "+f"(acc[mi][ni][2]), "+f"(acc[mi][ni][3])
                    : "r"(a[mi][0]), "r"(a[mi][1]), "r"(a[mi][2]), "r"(a[mi][3]),
                      "r"(b[ni][0]), "r"(b[ni][1]));
            }
    }

    // Epilogue: bias + ReLU, bf16 store
#pragma unroll
    for (int mi = 0; mi < 2; mi++) {
#pragma unroll
        for (int half = 0; half < 2; half++) {
            int row = m0 + wm + mi * 16 + lr + half * 8;
            if (row >= M) continue;
            __nv_bfloat16* outp = C + (size_t)row * ldc;
#pragma unroll
            for (int ni = 0; ni < 4; ni++) {
                int col = n0 + wn + ni * 8 + lc * 2;
                if (col >= N) continue;
                float v0 = fmaxf(acc[mi][ni][half * 2 + 0] + bias[col],     0.f);
                float v1 = fmaxf(acc[mi][ni][half * 2 + 1] + bias[col + 1], 0.f);
                *reinterpret_cast<__nv_bfloat162*>(outp + col) =
                    __floats2bfloat162_rn(v0, v1);
            }
        }
    }
}

// ==================================================================
// bf16 GEMM — R14 proven (BK=64, 2-stage, single barrier per k-iter).
// SCATTER=0: bf16 store; SCATTER=1: red.v2.f32 scatter.
// ==================================================================
#define BKB 64

template<int SCATTER>
__global__ __launch_bounds__(256, 4)
void gemm_bf16(const __nv_bfloat16* __restrict__ A,
               const __nv_bfloat16* __restrict__ Wt,
               const float* __restrict__ bias,
               void* __restrict__ Cv,
               const int* __restrict__ idx,
               int M, int Kp, int N, int lda, int ldc, int do_relu)
{
    __shared__ __align__(16) __nv_bfloat16 As[2][BM][SSB];
    __shared__ __align__(16) __nv_bfloat16 Ws[2][BN][SSB];

    const int tid  = threadIdx.x;
    const int warp = tid >> 5;
    const int lane = tid & 31;
    const int wm = (warp & 3) * 32;
    const int wn = (warp >> 2) * 32;
    const int n0 = blockIdx.x * BN;   // N-tile fastest => A reuse in L2
    const int m0 = blockIdx.y * BM;

    const int lr = lane >> 2;
    const int lc = lane & 3;

    const int aRowOff = lane & 15;
    const int aColOff = (lane >> 4) << 3;
    const int t8 = lane >> 3, r8 = lane & 7;
    const int bRowOff = ((t8 >> 1) << 3) + r8;
    const int bColOff = (t8 & 1) << 3;

    const uint32_t As32 = (uint32_t)__cvta_generic_to_shared(&As[0][0][0]);
    const uint32_t Ws32 = (uint32_t)__cvta_generic_to_shared(&Ws[0][0][0]);

    auto loadA = [&](int k0, int buf) {
#pragma unroll
        for (int i = 0; i < 4; i++) {
            int c = tid + i * 256;
            int mm = c >> 3, kc = (c & 7) * 8;
            bool ok = (m0 + mm) < M && (k0 + kc) < Kp;
            cp_async16(&As[buf][mm][kc],
                       A + (size_t)(ok ? (m0 + mm) : 0) * lda + k0 + kc, ok);
        }
    };
    auto loadW = [&](int k0, int buf) {
#pragma unroll
        for (int i = 0; i < 2; i++) {
            int c = tid + i * 256;
            int nn = c >> 3, kc = (c & 7) * 8;
            bool ok = (n0 + nn) < N && (k0 + kc) < Kp;
            cp_async16(&Ws[buf][nn][kc],
                       Wt + (size_t)(ok ? (n0 + nn) : 0) * Kp + k0 + kc, ok);
        }
    };

    float acc[2][4][4];
#pragma unroll
    for (int mi = 0; mi < 2; mi++)
#pragma unroll
        for (int ni = 0; ni < 4; ni++)
#pragma unroll
            for (int r = 0; r < 4; r++) acc[mi][ni][r] = 0.f;

    const int nsteps = (Kp + BKB - 1) / BKB;

    loadA(0, 0);
    loadW(0, 0);
    cp_async_commit();

    for (int s = 0; s < nsteps; s++) {
        const int buf = s & 1;
        cp_async_wait<0>();       // g_s complete (only pending group)
        __syncthreads();          // publish g_s; reads of other buf done

        if (s + 1 < nsteps) {     // prefetch g_{s+1} into the other buffer
            loadA((s + 1) * BKB, buf ^ 1);
            loadW((s + 1) * BKB, buf ^ 1);
            cp_async_commit();
        }

        const uint32_t aBufBase = As32 + (uint32_t)buf * (BM * SSB * 2);
        const uint32_t wBufBase = Ws32 + (uint32_t)buf * (BN * SSB * 2);

#pragma unroll
        for (int ks = 0; ks < BKB; ks += 16) {
            uint32_t a[2][4], b[4][2];
#pragma unroll
            for (int mi = 0; mi < 2; mi++) {
                uint32_t addr = aBufBase +
                    (uint32_t)(((wm + mi * 16 + aRowOff) * SSB + ks + aColOff) * 2);
                ldsm_x4(a[mi][0], a[mi][1], a[mi][2], a[mi][3], addr);
            }
#pragma unroll
            for (int p = 0; p < 2; p++) {
                uint32_t addr = wBufBase +
                    (uint32_t)(((wn + p * 16 + bRowOff) * SSB + ks + bColOff) * 2);
                ldsm_x4(b[2 * p][0], b[2 * p][1], b[2 * p + 1][0], b[2 * p + 1][1], addr);
            }
#pragma unroll
            for (int mi = 0; mi < 2; mi++)
#pragma unroll
                for (int ni = 0; ni < 4; ni++) {
                    asm volatile(
                        "mma.sync.aligned.m16n8k16.row.col.f32.bf16.bf16.f32 "
                        "{%0,%1,%2,%3}, {%4,%5,%6,%7}, {%8,%9}, {%0,%1,%2,%3};\n"
                        : "+f"(acc[mi][ni][0]), "+f"(acc[mi][ni][1]),
                          "+f"(acc[mi][ni][2]), "+f"(acc[mi][ni][3])
                        : "r"(a[mi][0]), "r"(a[mi][1]), "r"(a[mi][2]), "r"(a[mi][3]),
                          "r"(b[ni][0]), "r"(b[ni][1]));
                }
        }
    }

    // Epilogue
#pragma unroll
    for (int mi = 0; mi < 2; mi++) {
#pragma unroll
        for (int half = 0; half < 2; half++) {
            int row = m0 + wm + mi * 16 + lr + half * 8;
            if (row >= M) continue;
            long long obase;
            if (SCATTER) obase = (long long)idx[row] * ldc;
            else         obase = (long long)row * ldc;
#pragma unroll
            for (int ni = 0; ni < 4; ni++) {
                int col = n0 + wn + ni * 8 + lc * 2;
                if (col >= N) continue;  // N even => pair valid
                float v0 = acc[mi][ni][half * 2 + 0] + bias[col];
                float v1 = acc[mi][ni][half * 2 + 1] + bias[col + 1];
                if (do_relu) { v0 = fmaxf(v0, 0.f); v1 = fmaxf(v1, 0.f); }
                if (SCATTER) {
                    red_add_v2((float*)Cv + obase + col, v0, v1);
                } else {
                    __nv_bfloat162 pk = __floats2bfloat162_rn(v0, v1);
                    *reinterpret_cast<__nv_bfloat162*>(
                        (__nv_bfloat16*)Cv + obase + col) = pk;
                }
            }
        }
    }
}

// ==================================================================
// tf32 GEMM (node L1 only): fp32 A (cvt at fragment), bf16 output.
// Single-barrier mainloop.
// ==================================================================
#define BKT 32
#define SST 36

__global__ __launch_bounds__(256, 4)
void gemm_tf32_l1(const float* __restrict__ A,
                  const float* __restrict__ Wt,
                  const float* __restrict__ bias,
                  __nv_bfloat16* __restrict__ C,
                  int M, int K, int N, int ldc)
{
    __shared__ __align__(16) float As[2][BM][SST];
    __shared__ __align__(16) float Ws[2][BN][SST];

    const int tid  = threadIdx.x;
    const int warp = tid >> 5;
    const int lane = tid & 31;
    const int wm = (warp & 3) * 32;
    const int wn = (warp >> 2) * 32;
    const int n0 = blockIdx.x * BN;
    const int m0 = blockIdx.y * BM;

    const int lr = lane >> 2;
    const int lc = lane & 3;

    const int t8 = lane >> 3;
    const int r8 = lane & 7;
    const int aRowOff = ((t8 & 1) << 3) + r8;
    const int aColOff = (t8 >> 1) << 2;
    const int bRowOff = ((t8 >> 1) << 3) + r8;
    const int bColOff = (t8 & 1) << 2;

    const uint32_t As32 = (uint32_t)__cvta_generic_to_shared(&As[0][0][0]);
    const uint32_t Ws32 = (uint32_t)__cvta_generic_to_shared(&Ws[0][0][0]);

    auto loadA = [&](int k0, int buf) {
#pragma unroll
        for (int i = 0; i < 4; i++) {
            int c = tid + i * 256;
            int mm = c >> 3, kc = (c & 7) * 4;
            bool ok = (m0 + mm) < M && (k0 + kc) < K;
            cp_async16(&As[buf][mm][kc],
                       A + (size_t)(ok ? (m0 + mm) : 0) * K + k0 + kc, ok);
        }
    };
    auto loadW = [&](int k0, int buf) {
#pragma unroll
        for (int i = 0; i < 2; i++) {
            int c = tid + i * 256;
            int nn = c >> 3, kc = (c & 7) * 4;
            bool ok = (n0 + nn) < N && (k0 + kc) < K;
            cp_async16(&Ws[buf][nn][kc],
                       Wt + (size_t)(ok ? (n0 + nn) : 0) * K + k0 + kc, ok);
        }
    };

    float acc[2][4][4];
#pragma unroll
    for (int mi = 0; mi < 2; mi++)
#pragma unroll
        for (int ni = 0; ni < 4; ni++)
#pragma unroll
            for (int r = 0; r < 4; r++) acc[mi][ni][r] = 0.f;

    const int nsteps = (K + BKT - 1) / BKT;

    loadA(0, 0);
    loadW(0, 0);
    cp_async_commit();

    for (int s = 0; s < nsteps; s++) {
        const int buf = s & 1;
        cp_async_wait<0>();
        __syncthreads();

        if (s + 1 < nsteps) {
            loadA((s + 1) * BKT, buf ^ 1);
            loadW((s + 1) * BKT, buf ^ 1);
            cp_async_commit();
        }

        const uint32_t aBufBase = As32 + (uint32_t)buf * (BM * SST * 4);
        const uint32_t wBufBase = Ws32 + (uint32_t)buf * (BN * SST * 4);

#pragma unroll
        for (int ks = 0; ks < BKT; ks += 8) {
            uint32_t a[2][4], b[4][2];
#pragma unroll
            for (int mi = 0; mi < 2; mi++) {
                uint32_t addr = aBufBase +
                    (uint32_t)(((wm + mi * 16 + aRowOff) * SST + ks + aColOff) * 4);
                ldsm_x4(a[mi][0], a[mi][1], a[mi][2], a[mi][3], addr);
#pragma unroll
                for (int q = 0; q < 4; q++)
                    a[mi][q] = f2tf32(__uint_as_float(a[mi][q]));
            }
#pragma unroll
            for (int p = 0; p < 2; p++) {
                uint32_t addr = wBufBase +
                    (uint32_t)(((wn + p * 16 + bRowOff) * SST + ks + bColOff) * 4);
                ldsm_x4(b[2 * p][0], b[2 * p][1], b[2 * p + 1][0], b[2 * p + 1][1], addr);
            }
#pragma unroll
            for (int mi = 0; mi < 2; mi++)
#pragma unroll
                for (int ni = 0; ni < 4; ni++) {
                    asm volatile(
                        "mma.sync.aligned.m16n8k8.row.col.f32.tf32.tf32.f32 "
                        "{%0,%1,%2,%3}, {%4,%5,%6,%7}, {%8,%9}, {%0,%1,%2,%3};\n"
                        : "+f"(acc[mi][ni][0]), "+f"(acc[mi][ni][1]),
                          "+f"(acc[mi][ni][2]), "+f"(acc[mi][ni][3])
                        : "r"(a[mi][0]), "r"(a[mi][1]), "r"(a[mi][2]), "r"(a[mi][3]),
                          "r"(b[ni][0]), "r"(b[ni][1]));
                }
        }
    }

    // Epilogue: bias + ReLU, store bf16 (ldc stride, pads untouched)
#pragma unroll
    for (int mi = 0; mi < 2; mi++) {
#pragma unroll
        for (int half = 0; half < 2; half++) {
            int row = m0 + wm + mi * 16 + lr + half * 8;
            if (row >= M) continue;
            __nv_bfloat16* outp = C + (size_t)row * ldc;
#pragma unroll
            for (int ni = 0; ni < 4; ni++) {
                int col = n0 + wn + ni * 8 + lc * 2;
                if (col >= N) continue;   // N even => pair valid
                float v0 = fmaxf(acc[mi][ni][half * 2 + 0] + bias[col],     0.f);
                float v1 = fmaxf(acc[mi][ni][half * 2 + 1] + bias[col + 1], 0.f);
                *reinterpret_cast<__nv_bfloat162*>(outp + col) =
                    __floats2bfloat162_rn(v0, v1);
            }
        }
    }
}

// ------------------------------------------------------------------
// Pool count + final linear
// ------------------------------------------------------------------
__global__ void pool_cnt_kernel(const int* __restrict__ batch,
                                float* __restrict__ gcnt, int Nn)
{
    int n = blockIdx.x * blockDim.x + threadIdx.x;
    if (n >= Nn) return;
    atomicAdd(&gcnt[batch[n]], 1.0f);
}

__global__ void final_kernel(const float* __restrict__ gsum,
                             const float* __restrict__ gcnt,
                             const float* __restrict__ lw,
                             const float* __restrict__ lb,
                             float* __restrict__ out)
{
    int t = threadIdx.x;
    if (t >= NGRAPH * NPRED) return;
    int g = t / NPRED;
    int p = t % NPRED;
    float inv = 1.0f / fmaxf(gcnt[g], 1.0f);
    float s = 0.f;
    for (int k = 0; k < HID; k++)
        s = fmaf(gsum[g * HID + k] * inv, lw[k * NPRED + p], s);
    out[t] = s + lb[p];
}

// ------------------------------------------------------------------
// Launch
// ------------------------------------------------------------------
static inline int cdiv(int a, int b) { return (a + b - 1) / b; }

extern "C" void kernel_launch(void* const* d_in, const int* in_sizes, int n_in,
                              void* d_out, int out_size)
{
    const float* x   = (const float*)d_in[0];
    const int*   ei  = (const int*)d_in[1];
    const float* ea  = (const float*)d_in[2];
    const int*   bat = (const int*)d_in[3];
    const float* mw1 = (const float*)d_in[4];
    const float* mb1 = (const float*)d_in[5];
    const float* mw2 = (const float*)d_in[6];
    const float* mb2 = (const float*)d_in[7];
    const float* mw3 = (const float*)d_in[8];
    const float* mb3 = (const float*)d_in[9];
    const float* mw4 = (const float*)d_in[10];
    const float* mb4 = (const float*)d_in[11];
    const float* nw1 = (const float*)d_in[12];
    const float* nb1 = (const float*)d_in[13];
    const float* nw2 = (const float*)d_in[14];
    const float* nb2 = (const float*)d_in[15];
    const float* nw3 = (const float*)d_in[16];
    const float* nb3 = (const float*)d_in[17];
    const float* nw4 = (const float*)d_in[18];
    const float* nb4 = (const float*)d_in[19];
    const float* lw  = (const float*)d_in[20];
    const float* lb  = (const float*)d_in[21];
    float* out = (float*)d_out;

    const int E  = in_sizes[1] / 2;
    const int Nn = in_sizes[0] / N_NF;
    const int* src = ei;
    const int* dst = ei + E;

    __nv_bfloat16 *bbuf1, *bbuf2, *wbf;
    float *aggr, *gsum, *gcnt, *wnd;
    cudaGetSymbolAddress((void**)&bbuf1, g_bbuf1);
    cudaGetSymbolAddress((void**)&bbuf2, g_bbuf2);
    cudaGetSymbolAddress((void**)&aggr,  g_aggr);
    cudaGetSymbolAddress((void**)&gsum,  g_gsum);
    cudaGetSymbolAddress((void**)&gcnt,  g_gcnt);
    cudaGetSymbolAddress((void**)&wbf,   g_wbf);
    cudaGetSymbolAddress((void**)&wnd,   g_wnd);

    __nv_bfloat16* wb_mw1 = wbf;
    __nv_bfloat16* wb_mw2 = wb_mw1 + 300 * FEATP;
    __nv_bfloat16* wb_mw3 = wb_mw2 + 300 * HIDP;
    __nv_bfloat16* wb_mw4 = wb_mw3 + 300 * HIDP;
    __nv_bfloat16* wb_nw2 = wb_mw4 + 128 * HIDP;
    __nv_bfloat16* wb_nw3 = wb_nw2 + 300 * HIDP;
    __nv_bfloat16* wb_nw4 = wb_nw3 + 300 * HIDP;

    cudaMemsetAsync(aggr, 0, (size_t)N_NODES * MSGD * sizeof(float));
    cudaMemsetAsync(gsum, 0, (size_t)NGRAPH * HID * sizeof(float));
    cudaMemsetAsync(gcnt, 0, (size_t)NGRAPH * sizeof(float));

    // 0. One merged weight-prep launch
    {
        PrepArgs pa;
        pa.src[0] = mw1; pa.src[1] = mw2; pa.src[2] = mw3; pa.src[3] = mw4;
        pa.src[4] = nw2; pa.src[5] = nw3; pa.src[6] = nw4; pa.src[7] = nw1;
        pa.dstb[0] = wb_mw1; pa.dstb[1] = wb_mw2; pa.dstb[2] = wb_mw3;
        pa.dstb[3] = wb_mw4; pa.dstb[4] = wb_nw2; pa.dstb[5] = wb_nw3;
        pa.dstb[6] = wb_nw4;
        pa.dstf = wnd;
        pa.K[0] = FEAT; pa.K[1] = HID; pa.K[2] = HID; pa.K[3] = HID;
        pa.K[4] = HID;  pa.K[5] = HID; pa.K[6] = HID; pa.K[7] = 128;
        pa.N[0] = 300;  pa.N[1] = 300; pa.N[2] = 300; pa.N[3] = 128;
        pa.N[4] = 300;  pa.N[5] = 300; pa.N[6] = 300; pa.N[7] = 300;
        pa.Kp[0] = FEATP; pa.Kp[1] = HIDP; pa.Kp[2] = HIDP; pa.Kp[3] = HIDP;
        pa.Kp[4] = HIDP;  pa.Kp[5] = HIDP; pa.Kp[6] = HIDP;
        dim3 g(cdiv(300 * HIDP, 256), 8);
        prep_all_kernel<<<g, 256>>>(pa);
    }

    // 1. Edge MLP (bf16): fused gather+L1, then L2, L3, L4(scatter->aggr)
    {
        dim3 gridL1(cdiv(HID, BN), cdiv(E, BM));
        gemm_l1_fused<<<gridL1, 256>>>(x, src, dst, ea, wb_mw1, mb1, bbuf1,
                                       E, HID, HIDP);
        dim3 grid(cdiv(HID, BN), cdiv(E, BM));
        gemm_bf16<0><<<grid, 256>>>(bbuf1, wb_mw2, mb2, bbuf2, nullptr,
                                    E, HIDP, HID, HIDP, HIDP, 1);
        gemm_bf16<0><<<grid, 256>>>(bbuf2, wb_mw3, mb3, bbuf1, nullptr,
                                    E, HIDP, HID, HIDP, HIDP, 1);
        dim3 grid4(cdiv(MSGD, BN), cdiv(E, BM));
        gemm_bf16<1><<<grid4, 256>>>(bbuf1, wb_mw4, mb4, aggr, dst,
                                     E, HIDP, MSGD, HIDP, MSGD, 0);
    }

    // 2. Node MLP: L1 tf32 (fp32 aggr in, bf16 out), L2/L3 bf16,
    //    L4 bf16 with fp32 red scatter into gsum (pool)
    {
        dim3 grid(cdiv(HID, BN), cdiv(Nn, BM));
        gemm_tf32_l1<<<grid, 256>>>(aggr, wnd, nb1, bbuf2, Nn, MSGD, HID, HIDP);
        gemm_bf16<0><<<grid, 256>>>(bbuf2, wb_nw2, nb2, bbuf1, nullptr,
                                    Nn, HIDP, HID, HIDP, HIDP, 1);
        gemm_bf16<0><<<grid, 256>>>(bbuf1, wb_nw3, nb3, bbuf2, nullptr,
                                    Nn, HIDP, HID, HIDP, HIDP, 1);
        gemm_bf16<1><<<grid, 256>>>(bbuf2, wb_nw4, nb4, gsum, bat,
                                    Nn, HIDP, HID, HIDP, HID, 0);
    }

    // 3. Counts + final linear
    pool_cnt_kernel<<<cdiv(Nn, 256), 256>>>(bat, gcnt, Nn);
    final_kernel<<<1, 512>>>(gsum, gcnt, lw, lb, out);
}

// round 16
// speedup vs baseline: 1.0280x; 1.0280x over previous
#include <cuda_runtime.h>
#include <cuda_bf16.h>
#include <cstdint>

// Problem constants (match reference)
#define E_CNT   800000
#define N_NODES 50000
#define N_NF    16
#define N_EF    8
#define FEAT    40      // 2*N_NF + N_EF
#define FEATP   48      // padded to 8-half chunks
#define HID     300
#define HIDP    304     // padded
#define MSGD    128
#define NGRAPH  64
#define NPRED   8

// ------------------------------------------------------------------
// Scratch (device globals; zero-initialized, pads stay 0 forever)
// ------------------------------------------------------------------
__device__ __nv_bfloat16 g_bbuf1[(size_t)E_CNT * HIDP];
__device__ __nv_bfloat16 g_bbuf2[(size_t)E_CNT * HIDP];
__device__ float g_aggr[(size_t)N_NODES * MSGD];
__device__ float g_gsum[NGRAPH * HID];
__device__ float g_gcnt[NGRAPH];
// bf16 weights, transposed+padded [N][Kp]:
//   mw1[300][48], mw2/mw3[300][304], mw4[128][304],
//   nw2/nw3/nw4[300][304]
#define WBF_TOTAL (300*FEATP + 2*300*HIDP + 128*HIDP + 3*300*HIDP)
__device__ __nv_bfloat16 g_wbf[WBF_TOTAL];
// node L1 weight: fp32 tf32-rounded, transposed [300][128]
__device__ float g_wnd[300 * 128];

__device__ __forceinline__ uint32_t f2tf32(float v) {
    uint32_t t;
    asm("cvt.rna.tf32.f32 %0, %1;" : "=r"(t) : "f"(v));
    return t;
}
__device__ __forceinline__ uint32_t pack_bf2(float a, float b) {
    __nv_bfloat162 p = __floats2bfloat162_rn(a, b);
    return *reinterpret_cast<uint32_t*>(&p);
}

// ------------------------------------------------------------------
// Merged weight prep: grid.y = weight id (0-6 bf16, 7 tf32 nw1)
// ------------------------------------------------------------------
struct PrepArgs {
    const float* src[8];
    __nv_bfloat16* dstb[7];
    float* dstf;
    int K[8], N[8], Kp[7];
};

__global__ void prep_all_kernel(PrepArgs pa)
{
    int w = blockIdx.y;
    int i = blockIdx.x * blockDim.x + threadIdx.x;
    if (w < 7) {
        int K = pa.K[w], N = pa.N[w], Kp = pa.Kp[w];
        if (i >= N * Kp) return;
        int n = i / Kp, k = i % Kp;
        pa.dstb[w][i] = (k < K) ? __float2bfloat16(pa.src[w][(size_t)k * N + n])
                                : __float2bfloat16(0.f);
    } else {
        int K = pa.K[7], N = pa.N[7];
        if (i >= K * N) return;
        int k = i / N, n = i % N;
        pa.dstf[(size_t)n * K + k] = __uint_as_float(f2tf32(pa.src[7][i]));
    }
}

// ------------------------------------------------------------------
// Async-copy / ldmatrix / atomic helpers
// ------------------------------------------------------------------
__device__ __forceinline__ void cp_async16(void* sptr, const void* gptr, bool pred)
{
    uint32_t saddr = (uint32_t)__cvta_generic_to_shared(sptr);
    int sz = pred ? 16 : 0;  // src-size 0 => 16B of zeros written
    asm volatile("cp.async.cg.shared.global [%0], [%1], 16, %2;\n"
                 :: "r"(saddr), "l"(gptr), "r"(sz));
}
__device__ __forceinline__ void cp_async_commit() {
    asm volatile("cp.async.commit_group;\n" ::: "memory");
}
template<int N_> __device__ __forceinline__ void cp_async_wait() {
    asm volatile("cp.async.wait_group %0;\n" :: "n"(N_) : "memory");
}
__device__ __forceinline__ void ldsm_x4(uint32_t& r0, uint32_t& r1,
                                        uint32_t& r2, uint32_t& r3, uint32_t saddr)
{
    asm volatile("ldmatrix.sync.aligned.m8n8.x4.shared.b16 {%0,%1,%2,%3}, [%4];\n"
                 : "=r"(r0), "=r"(r1), "=r"(r2), "=r"(r3) : "r"(saddr));
}
__device__ __forceinline__ void red_add_v2(float* addr, float a, float b)
{
    asm volatile("red.global.add.v2.f32 [%0], {%1, %2};\n"
                 :: "l"(addr), "f"(a), "f"(b) : "memory");
}

#define BM 128
#define BN 64
#define SSB 72   // smem row stride in halves (144B): LDSM conflict-free

// ==================================================================
// Fused gather + edge L1 (v2): ONE CTA per m-tile; CTA loops over
// all 5 n-tiles. Gather runs once per edge; full W1 resident in smem;
// A fragments hoisted to registers and reused across n-tiles.
// Dynamic smem: As[128][56] + Ws[320][56] bf16 = 50,176 B (4 CTAs/SM).
// ==================================================================
#define KL1   48
#define SSA1  56            // stride 112B; banks r*28 mod 32 distinct
#define NW1   320           // W rows incl. zero pad (n up to 319 touched)
#define L1_SMEM ((BM + NW1) * SSA1 * 2)

__global__ __launch_bounds__(256, 4)
void gemm_l1_fused(const float* __restrict__ x,
                   const int* __restrict__ srcI,
                   const int* __restrict__ dstI,
                   const float* __restrict__ ea,
                   const __nv_bfloat16* __restrict__ Wt,   // [300][48]
                   const float* __restrict__ bias,
                   __nv_bfloat16* __restrict__ C,
                   int M, int N, int ldc)
{
    extern __shared__ __align__(16) __nv_bfloat16 sm1[];
    __nv_bfloat16 (*As)[SSA1] = reinterpret_cast<__nv_bfloat16(*)[SSA1]>(sm1);
    __nv_bfloat16 (*Ws)[SSA1] = reinterpret_cast<__nv_bfloat16(*)[SSA1]>(sm1 + BM * SSA1);

    const int tid  = threadIdx.x;
    const int warp = tid >> 5;
    const int lane = tid & 31;
    const int wm = (warp & 3) * 32;
    const int wn = (warp >> 2) * 32;
    const int m0 = blockIdx.x * BM;

    const int lr = lane >> 2;
    const int lc = lane & 3;

    const int aRowOff = lane & 15;
    const int aColOff = (lane >> 4) << 3;
    const int t8 = lane >> 3, r8 = lane & 7;
    const int bRowOff = ((t8 >> 1) << 3) + r8;
    const int bColOff = (t8 & 1) << 3;

    const uint32_t As32 = (uint32_t)__cvta_generic_to_shared(&As[0][0]);
    const uint32_t Ws32 = (uint32_t)__cvta_generic_to_shared(&Ws[0][0]);

    // --- W1 resident: 320 rows x 6 chunks of 16B (rows>=300 zeroed) ---
#pragma unroll
    for (int i = 0; i < 8; i++) {
        int c = tid + i * 256;
        if (c < NW1 * 6) {
            int nn = c / 6, kc = (c % 6) * 8;
            bool ok = nn < N;
            cp_async16(&Ws[nn][kc], Wt + (size_t)(ok ? nn : 0) * KL1 + kc, ok);
        }
    }
    cp_async_commit();

    // --- Gather A tile once: 128 edges x 6 chunks (c5 = zero pad) ---
#pragma unroll
    for (int i = 0; i < 3; i++) {
        int u = tid + i * 256;
        int erow = u / 6, c = u % 6;
        int row = m0 + erow;
        uint4 o = make_uint4(0u, 0u, 0u, 0u);
        if (row < M && c < 5) {
            float4 v0, v1;
            if (c < 4) {
                int node = (c < 2) ? dstI[row] : srcI[row];
                const float4* xp = reinterpret_cast<const float4*>(x)
                                   + (size_t)node * 4 + (c & 1) * 2;
                v0 = xp[0]; v1 = xp[1];
            } else {
                const float4* epp = reinterpret_cast<const float4*>(ea)
                                    + (size_t)row * 2;
                v0 = epp[0]; v1 = epp[1];
            }
            o.x = pack_bf2(v0.x, v0.y); o.y = pack_bf2(v0.z, v0.w);
            o.z = pack_bf2(v1.x, v1.y); o.w = pack_bf2(v1.z, v1.w);
        }
        *reinterpret_cast<uint4*>(&As[erow][c * 8]) = o;
    }

    cp_async_wait<0>();
    __syncthreads();

    // --- Hoist A fragments (3 k-steps x 2 mi x 4 regs = 24 regs) ---
    uint32_t af[3][2][4];
#pragma unroll
    for (int kk = 0; kk < 3; kk++) {
#pragma unroll
        for (int mi = 0; mi < 2; mi++) {
            uint32_t addr = As32 +
                (uint32_t)(((wm + mi * 16 + aRowOff) * SSA1 + kk * 16 + aColOff) * 2);
            ldsm_x4(af[kk][mi][0], af[kk][mi][1], af[kk][mi][2], af[kk][mi][3], addr);
        }
    }

    // --- Loop over 5 n-tiles of 64 ---
#pragma unroll 1
    for (int nt = 0; nt < 5; nt++) {
        const int n0 = nt * 64;
        float acc[2][4][4];
#pragma unroll
        for (int mi = 0; mi < 2; mi++)
#pragma unroll
            for (int ni = 0; ni < 4; ni++)
#pragma unroll
                for (int r = 0; r < 4; r++) acc[mi][ni][r] = 0.f;

#pragma unroll
        for (int kk = 0; kk < 3; kk++) {
            uint32_t b[4][2];
#pragma unroll
            for (int p = 0; p < 2; p++) {
                uint32_t addr = Ws32 +
                    (uint32_t)(((n0 + wn + p * 16 + bRowOff) * SSA1
                               + kk * 16 + bColOff) * 2);
                ldsm_x4(b[2 * p][0], b[2 * p][1], b[2 * p + 1][0], b[2 * p + 1][1], addr);
            }
#pragma unroll
            for (int mi = 0; mi < 2; mi++)
#pragma unroll
                for (int ni = 0; ni < 4; ni++) {
                    asm volatile(
                        "mma.sync.aligned.m16n8k16.row.col.f32.bf16.bf16.f32 "
                        "{%0,%1,%2,%3}, {%4,%5,%6,%7}, {%8,%9}, {%0,%1,%2,%3};\n"
                        : "+f"(acc[mi][ni][0]), "+f"(acc[mi][ni][1]),
                          "+f"(acc[mi][ni][2]), "+f"(acc[mi][ni][3])
                        : "r"(af[kk][mi][0]), "r"(af[kk][mi][1]),
                          "r"(af[kk][mi][2]), "r"(af[kk][mi][3]),
                          "r"(b[ni][0]), "r"(b[ni][1]));
                }
        }

        // Epilogue for this n-tile: bias + ReLU, bf16 store
#pragma unroll
        for (int mi = 0; mi < 2; mi++) {
#pragma unroll
            for (int half = 0; half < 2; half++) {
                int row = m0 + wm + mi * 16 + lr + half * 8;
                if (row >= M) continue;
                __nv_bfloat16* outp = C + (size_t)row * ldc;
#pragma unroll
                for (int ni = 0; ni < 4; ni++) {
                    int col = n0 + wn + ni * 8 + lc * 2;
                    if (col >= N) continue;
                    float v0 = fmaxf(acc[mi][ni][half * 2 + 0] + bias[col],     0.f);
                    float v1 = fmaxf(acc[mi][ni][half * 2 + 1] + bias[col + 1], 0.f);
                    *reinterpret_cast<__nv_bfloat162*>(outp + col) =
                        __floats2bfloat162_rn(v0, v1);
                }
            }
        }
    }
}

// ==================================================================
// bf16 GEMM — R14 proven (BK=64, 2-stage, single barrier per k-iter).
// SCATTER=0: bf16 store; SCATTER=1: red.v2.f32 scatter.
// ==================================================================
#define BKB 64

template<int SCATTER>
__global__ __launch_bounds__(256, 4)
void gemm_bf16(const __nv_bfloat16* __restrict__ A,
               const __nv_bfloat16* __restrict__ Wt,
               const float* __restrict__ bias,
               void* __restrict__ Cv,
               const int* __restrict__ idx,
               int M, int Kp, int N, int lda, int ldc, int do_relu)
{
    __shared__ __align__(16) __nv_bfloat16 As[2][BM][SSB];
    __shared__ __align__(16) __nv_bfloat16 Ws[2][BN][SSB];

    const int tid  = threadIdx.x;
    const int warp = tid >> 5;
    const int lane = tid & 31;
    const int wm = (warp & 3) * 32;
    const int wn = (warp >> 2) * 32;
    const int n0 = blockIdx.x * BN;   // N-tile fastest => A reuse in L2
    const int m0 = blockIdx.y * BM;

    const int lr = lane >> 2;
    const int lc = lane & 3;

    const int aRowOff = lane & 15;
    const int aColOff = (lane >> 4) << 3;
    const int t8 = lane >> 3, r8 = lane & 7;
    const int bRowOff = ((t8 >> 1) << 3) + r8;
    const int bColOff = (t8 & 1) << 3;

    const uint32_t As32 = (uint32_t)__cvta_generic_to_shared(&As[0][0][0]);
    const uint32_t Ws32 = (uint32_t)__cvta_generic_to_shared(&Ws[0][0][0]);

    auto loadA = [&](int k0, int buf) {
#pragma unroll
        for (int i = 0; i < 4; i++) {
            int c = tid + i * 256;
            int mm = c >> 3, kc = (c & 7) * 8;
            bool ok = (m0 + mm) < M && (k0 + kc) < Kp;
            cp_async16(&As[buf][mm][kc],
                       A + (size_t)(ok ? (m0 + mm) : 0) * lda + k0 + kc, ok);
        }
    };
    auto loadW = [&](int k0, int buf) {
#pragma unroll
        for (int i = 0; i < 2; i++) {
            int c = tid + i * 256;
            int nn = c >> 3, kc = (c & 7) * 8;
            bool ok = (n0 + nn) < N && (k0 + kc) < Kp;
            cp_async16(&Ws[buf][nn][kc],
                       Wt + (size_t)(ok ? (n0 + nn) : 0) * Kp + k0 + kc, ok);
        }
    };

    float acc[2][4][4];
#pragma unroll
    for (int mi = 0; mi < 2; mi++)
#pragma unroll
        for (int ni = 0; ni < 4; ni++)
#pragma unroll
            for (int r = 0; r < 4; r++) acc[mi][ni][r] = 0.f;

    const int nsteps = (Kp + BKB - 1) / BKB;

    loadA(0, 0);
    loadW(0, 0);
    cp_async_commit();

    for (int s = 0; s < nsteps; s++) {
        const int buf = s & 1;
        cp_async_wait<0>();       // g_s complete (only pending group)
        __syncthreads();          // publish g_s; reads of other buf done

        if (s + 1 < nsteps) {     // prefetch g_{s+1} into the other buffer
            loadA((s + 1) * BKB, buf ^ 1);
            loadW((s + 1) * BKB, buf ^ 1);
            cp_async_commit();
        }

        const uint32_t aBufBase = As32 + (uint32_t)buf * (BM * SSB * 2);
        const uint32_t wBufBase = Ws32 + (uint32_t)buf * (BN * SSB * 2);

#pragma unroll
        for (int ks = 0; ks < BKB; ks += 16) {
            uint32_t a[2][4], b[4][2];
#pragma unroll
            for (int mi = 0; mi < 2; mi++) {
                uint32_t addr = aBufBase +
                    (uint32_t)(((wm + mi * 16 + aRowOff) * SSB + ks + aColOff) * 2);
                ldsm_x4(a[mi][0], a[mi][1], a[mi][2], a[mi][3], addr);
            }
#pragma unroll
            for (int p = 0; p < 2; p++) {
                uint32_t addr = wBufBase +
                    (uint32_t)(((wn + p * 16 + bRowOff) * SSB + ks + bColOff) * 2);
                ldsm_x4(b[2 * p][0], b[2 * p][1], b[2 * p + 1][0], b[2 * p + 1][1], addr);
            }
#pragma unroll
            for (int mi = 0; mi < 2; mi++)
#pragma unroll
                for (int ni = 0; ni < 4; ni++) {
                    asm volatile(
                        "mma.sync.aligned.m16n8k16.row.col.f32.bf16.bf16.f32 "
                        "{%0,%1,%2,%3}, {%4,%5,%6,%7}, {%8,%9}, {%0,%1,%2,%3};\n"
                        : "+f"(acc[mi][ni][0]), "+f"(acc[mi][ni][1]),
                          "+f"(acc[mi][ni][2]), "+f"(acc[mi][ni][3])
                        : "r"(a[mi][0]), "r"(a[mi][1]), "r"(a[mi][2]), "r"(a[mi][3]),
                          "r"(b[ni][0]), "r"(b[ni][1]));
                }
        }
    }

    // Epilogue
#pragma unroll
    for (int mi = 0; mi < 2; mi++) {
#pragma unroll
        for (int half = 0; half < 2; half++) {
            int row = m0 + wm + mi * 16 + lr + half * 8;
            if (row >= M) continue;
            long long obase;
            if (SCATTER) obase = (long long)idx[row] * ldc;
            else         obase = (long long)row * ldc;
#pragma unroll
            for (int ni = 0; ni < 4; ni++) {
                int col = n0 + wn + ni * 8 + lc * 2;
                if (col >= N) continue;  // N even => pair valid
                float v0 = acc[mi][ni][half * 2 + 0] + bias[col];
                float v1 = acc[mi][ni][half * 2 + 1] + bias[col + 1];
                if (do_relu) { v0 = fmaxf(v0, 0.f); v1 = fmaxf(v1, 0.f); }
                if (SCATTER) {
                    red_add_v2((float*)Cv + obase + col, v0, v1);
                } else {
                    __nv_bfloat162 pk = __floats2bfloat162_rn(v0, v1);
                    *reinterpret_cast<__nv_bfloat162*>(
                        (__nv_bfloat16*)Cv + obase + col) = pk;
                }
            }
        }
    }
}

// ==================================================================
// tf32 GEMM (node L1 only): fp32 A (cvt at fragment), bf16 output.
// Single-barrier mainloop.
// ==================================================================
#define BKT 32
#define SST 36

__global__ __launch_bounds__(256, 4)
void gemm_tf32_l1(const float* __restrict__ A,
                  const float* __restrict__ Wt,
                  const float* __restrict__ bias,
                  __nv_bfloat16* __restrict__ C,
                  int M, int K, int N, int ldc)
{
    __shared__ __align__(16) float As[2][BM][SST];
    __shared__ __align__(16) float Ws[2][BN][SST];

    const int tid  = threadIdx.x;
    const int warp = tid >> 5;
    const int lane = tid & 31;
    const int wm = (warp & 3) * 32;
    const int wn = (warp >> 2) * 32;
    const int n0 = blockIdx.x * BN;
    const int m0 = blockIdx.y * BM;

    const int lr = lane >> 2;
    const int lc = lane & 3;

    const int t8 = lane >> 3;
    const int r8 = lane & 7;
    const int aRowOff = ((t8 & 1) << 3) + r8;
    const int aColOff = (t8 >> 1) << 2;
    const int bRowOff = ((t8 >> 1) << 3) + r8;
    const int bColOff = (t8 & 1) << 2;

    const uint32_t As32 = (uint32_t)__cvta_generic_to_shared(&As[0][0][0]);
    const uint32_t Ws32 = (uint32_t)__cvta_generic_to_shared(&Ws[0][0][0]);

    auto loadA = [&](int k0, int buf) {
#pragma unroll
        for (int i = 0; i < 4; i++) {
            int c = tid + i * 256;
            int mm = c >> 3, kc = (c & 7) * 4;
            bool ok = (m0 + mm) < M && (k0 + kc) < K;
            cp_async16(&As[buf][mm][kc],
                       A + (size_t)(ok ? (m0 + mm) : 0) * K + k0 + kc, ok);
        }
    };
    auto loadW = [&](int k0, int buf) {
#pragma unroll
        for (int i = 0; i < 2; i++) {
            int c = tid + i * 256;
            int nn = c >> 3, kc = (c & 7) * 4;
            bool ok = (n0 + nn) < N && (k0 + kc) < K;
            cp_async16(&Ws[buf][nn][kc],
                       Wt + (size_t)(ok ? (n0 + nn) : 0) * K + k0 + kc, ok);
        }
    };

    float acc[2][4][4];
#pragma unroll
    for (int mi = 0; mi < 2; mi++)
#pragma unroll
        for (int ni = 0; ni < 4; ni++)
#pragma unroll
            for (int r = 0; r < 4; r++) acc[mi][ni][r] = 0.f;

    const int nsteps = (K + BKT - 1) / BKT;

    loadA(0, 0);
    loadW(0, 0);
    cp_async_commit();

    for (int s = 0; s < nsteps; s++) {
        const int buf = s & 1;
        cp_async_wait<0>();
        __syncthreads();

        if (s + 1 < nsteps) {
            loadA((s + 1) * BKT, buf ^ 1);
            loadW((s + 1) * BKT, buf ^ 1);
            cp_async_commit();
        }

        const uint32_t aBufBase = As32 + (uint32_t)buf * (BM * SST * 4);
        const uint32_t wBufBase = Ws32 + (uint32_t)buf * (BN * SST * 4);

#pragma unroll
        for (int ks = 0; ks < BKT; ks += 8) {
            uint32_t a[2][4], b[4][2];
#pragma unroll
            for (int mi = 0; mi < 2; mi++) {
                uint32_t addr = aBufBase +
                    (uint32_t)(((wm + mi * 16 + aRowOff) * SST + ks + aColOff) * 4);
                ldsm_x4(a[mi][0], a[mi][1], a[mi][2], a[mi][3], addr);
#pragma unroll
                for (int q = 0; q < 4; q++)
                    a[mi][q] = f2tf32(__uint_as_float(a[mi][q]));
            }
#pragma unroll
            for (int p = 0; p < 2; p++) {
                uint32_t addr = wBufBase +
                    (uint32_t)(((wn + p * 16 + bRowOff) * SST + ks + bColOff) * 4);
                ldsm_x4(b[2 * p][0], b[2 * p][1], b[2 * p + 1][0], b[2 * p + 1][1], addr);
            }
#pragma unroll
            for (int mi = 0; mi < 2; mi++)
#pragma unroll
                for (int ni = 0; ni < 4; ni++) {
                    asm volatile(
                        "mma.sync.aligned.m16n8k8.row.col.f32.tf32.tf32.f32 "
                        "{%0,%1,%2,%3}, {%4,%5,%6,%7}, {%8,%9}, {%0,%1,%2,%3};\n"
                        : "+f"(acc[mi][ni][0]), "+f"(acc[mi][ni][1]),
                          "+f"(acc[mi][ni][2]), "+f"(acc[mi][ni][3])
                        : "r"(a[mi][0]), "r"(a[mi][1]), "r"(a[mi][2]), "r"(a[mi][3]),
                          "r"(b[ni][0]), "r"(b[ni][1]));
                }
        }
    }

    // Epilogue: bias + ReLU, store bf16 (ldc stride, pads untouched)
#pragma unroll
    for (int mi = 0; mi < 2; mi++) {
#pragma unroll
        for (int half = 0; half < 2; half++) {
            int row = m0 + wm + mi * 16 + lr + half * 8;
            if (row >= M) continue;
            __nv_bfloat16* outp = C + (size_t)row * ldc;
#pragma unroll
            for (int ni = 0; ni < 4; ni++) {
                int col = n0 + wn + ni * 8 + lc * 2;
                if (col >= N) continue;   // N even => pair valid
                float v0 = fmaxf(acc[mi][ni][half * 2 + 0] + bias[col],     0.f);
                float v1 = fmaxf(acc[mi][ni][half * 2 + 1] + bias[col + 1], 0.f);
                *reinterpret_cast<__nv_bfloat162*>(outp + col) =
                    __floats2bfloat162_rn(v0, v1);
            }
        }
    }
}

// ------------------------------------------------------------------
// Pool count + final linear
// ------------------------------------------------------------------
__global__ void pool_cnt_kernel(const int* __restrict__ batch,
                                float* __restrict__ gcnt, int Nn)
{
    int n = blockIdx.x * blockDim.x + threadIdx.x;
    if (n >= Nn) return;
    atomicAdd(&gcnt[batch[n]], 1.0f);
}

__global__ void final_kernel(const float* __restrict__ gsum,
                             const float* __restrict__ gcnt,
                             const float* __restrict__ lw,
                             const float* __restrict__ lb,
                             float* __restrict__ out)
{
    int t = threadIdx.x;
    if (t >= NGRAPH * NPRED) return;
    int g = t / NPRED;
    int p = t % NPRED;
    float inv = 1.0f / fmaxf(gcnt[g], 1.0f);
    float s = 0.f;
    for (int k = 0; k < HID; k++)
        s = fmaf(gsum[g * HID + k] * inv, lw[k * NPRED + p], s);
    out[t] = s + lb[p];
}

// ------------------------------------------------------------------
// Launch
// ------------------------------------------------------------------
static inline int cdiv(int a, int b) { return (a + b - 1) / b; }

extern "C" void kernel_launch(void* const* d_in, const int* in_sizes, int n_in,
                              void* d_out, int out_size)
{
    const float* x   = (const float*)d_in[0];
    const int*   ei  = (const int*)d_in[1];
    const float* ea  = (const float*)d_in[2];
    const int*   bat = (const int*)d_in[3];
    const float* mw1 = (const float*)d_in[4];
    const float* mb1 = (const float*)d_in[5];
    const float* mw2 = (const float*)d_in[6];
    const float* mb2 = (const float*)d_in[7];
    const float* mw3 = (const float*)d_in[8];
    const float* mb3 = (const float*)d_in[9];
    const float* mw4 = (const float*)d_in[10];
    const float* mb4 = (const float*)d_in[11];
    const float* nw1 = (const float*)d_in[12];
    const float* nb1 = (const float*)d_in[13];
    const float* nw2 = (const float*)d_in[14];
    const float* nb2 = (const float*)d_in[15];
    const float* nw3 = (const float*)d_in[16];
    const float* nb3 = (const float*)d_in[17];
    const float* nw4 = (const float*)d_in[18];
    const float* nb4 = (const float*)d_in[19];
    const float* lw  = (const float*)d_in[20];
    const float* lb  = (const float*)d_in[21];
    float* out = (float*)d_out;

    const int E  = in_sizes[1] / 2;
    const int Nn = in_sizes[0] / N_NF;
    const int* src = ei;
    const int* dst = ei + E;

    __nv_bfloat16 *bbuf1, *bbuf2, *wbf;
    float *aggr, *gsum, *gcnt, *wnd;
    cudaGetSymbolAddress((void**)&bbuf1, g_bbuf1);
    cudaGetSymbolAddress((void**)&bbuf2, g_bbuf2);
    cudaGetSymbolAddress((void**)&aggr,  g_aggr);
    cudaGetSymbolAddress((void**)&gsum,  g_gsum);
    cudaGetSymbolAddress((void**)&gcnt,  g_gcnt);
    cudaGetSymbolAddress((void**)&wbf,   g_wbf);
    cudaGetSymbolAddress((void**)&wnd,   g_wnd);

    __nv_bfloat16* wb_mw1 = wbf;
    __nv_bfloat16* wb_mw2 = wb_mw1 + 300 * FEATP;
    __nv_bfloat16* wb_mw3 = wb_mw2 + 300 * HIDP;
    __nv_bfloat16* wb_mw4 = wb_mw3 + 300 * HIDP;
    __nv_bfloat16* wb_nw2 = wb_mw4 + 128 * HIDP;
    __nv_bfloat16* wb_nw3 = wb_nw2 + 300 * HIDP;
    __nv_bfloat16* wb_nw4 = wb_nw3 + 300 * HIDP;

    cudaFuncSetAttribute(gemm_l1_fused,
                         cudaFuncAttributeMaxDynamicSharedMemorySize, L1_SMEM);

    cudaMemsetAsync(aggr, 0, (size_t)N_NODES * MSGD * sizeof(float));
    cudaMemsetAsync(gsum, 0, (size_t)NGRAPH * HID * sizeof(float));
    cudaMemsetAsync(gcnt, 0, (size_t)NGRAPH * sizeof(float));

    // 0. One merged weight-prep launch
    {
        PrepArgs pa;
        pa.src[0] = mw1; pa.src[1] = mw2; pa.src[2] = mw3; pa.src[3] = mw4;
        pa.src[4] = nw2; pa.src[5] = nw3; pa.src[6] = nw4; pa.src[7] = nw1;
        pa.dstb[0] = wb_mw1; pa.dstb[1] = wb_mw2; pa.dstb[2] = wb_mw3;
        pa.dstb[3] = wb_mw4; pa.dstb[4] = wb_nw2; pa.dstb[5] = wb_nw3;
        pa.dstb[6] = wb_nw4;
        pa.dstf = wnd;
        pa.K[0] = FEAT; pa.K[1] = HID; pa.K[2] = HID; pa.K[3] = HID;
        pa.K[4] = HID;  pa.K[5] = HID; pa.K[6] = HID; pa.K[7] = 128;
        pa.N[0] = 300;  pa.N[1] = 300; pa.N[2] = 300; pa.N[3] = 128;
        pa.N[4] = 300;  pa.N[5] = 300; pa.N[6] = 300; pa.N[7] = 300;
        pa.Kp[0] = FEATP; pa.Kp[1] = HIDP; pa.Kp[2] = HIDP; pa.Kp[3] = HIDP;
        pa.Kp[4] = HIDP;  pa.Kp[5] = HIDP; pa.Kp[6] = HIDP;
        dim3 g(cdiv(300 * HIDP, 256), 8);
        prep_all_kernel<<<g, 256>>>(pa);
    }

    // 1. Edge MLP (bf16): fused gather+L1 (1 CTA per m-tile, n-loop),
    //    then L2, L3, L4 (scatter -> aggr)
    {
        gemm_l1_fused<<<cdiv(E, BM), 256, L1_SMEM>>>(x, src, dst, ea,
                                                     wb_mw1, mb1, bbuf1,
                                                     E, HID, HIDP);
        dim3 grid(cdiv(HID, BN), cdiv(E, BM));
        gemm_bf16<0><<<grid, 256>>>(bbuf1, wb_mw2, mb2, bbuf2, nullptr,
                                    E, HIDP, HID, HIDP, HIDP, 1);
        gemm_bf16<0><<<grid, 256>>>(bbuf2, wb_mw3, mb3, bbuf1, nullptr,
                                    E, HIDP, HID, HIDP, HIDP, 1);
        dim3 grid4(cdiv(MSGD, BN), cdiv(E, BM));
        gemm_bf16<1><<<grid4, 256>>>(bbuf1, wb_mw4, mb4, aggr, dst,
                                     E, HIDP, MSGD, HIDP, MSGD, 0);
    }

    // 2. Node MLP: L1 tf32 (fp32 aggr in, bf16 out), L2/L3 bf16,
    //    L4 bf16 with fp32 red scatter into gsum (pool)
    {
        dim3 grid(cdiv(HID, BN), cdiv(Nn, BM));
        gemm_tf32_l1<<<grid, 256>>>(aggr, wnd, nb1, bbuf2, Nn, MSGD, HID, HIDP);
        gemm_bf16<0><<<grid, 256>>>(bbuf2, wb_nw2, nb2, bbuf1, nullptr,
                                    Nn, HIDP, HID, HIDP, HIDP, 1);
        gemm_bf16<0><<<grid, 256>>>(bbuf1, wb_nw3, nb3, bbuf2, nullptr,
                                    Nn, HIDP, HID, HIDP, HIDP, 1);
        gemm_bf16<1><<<grid, 256>>>(bbuf2, wb_nw4, nb4, gsum, bat,
                                    Nn, HIDP, HID, HIDP, HID, 0);
    }

    // 3. Counts + final linear
    pool_cnt_kernel<<<cdiv(Nn, 256), 256>>>(bat, gcnt, Nn);
    final_kernel<<<1, 512>>>(gsum, gcnt, lw, lb, out);
}